// round 4
// baseline (speedup 1.0000x reference)
#include <cuda_runtime.h>
#include <cuda_bf16.h>

#define NU 100000
#define NI 100000
#define EE 1600000
#define C  128
#define C2 (C / 2)
#define NCV (NU * C2)       // bfloat162 elements per table (NU==NI)
#define LN_EPS 1e-5f

#define SCAN_T     256
#define SCAN_E     4
#define SCAN_CHUNK (SCAN_T * SCAN_E)   // 1024
#define NBLK ((NU + SCAN_CHUNK - 1) / SCAN_CHUNK)   // 98 (NU==NI)

// ---- scratch (allocation-free rule: device globals) ----
__device__ int   g_deg_u[NU];
__device__ int   g_deg_i[NI];
__device__ int   g_off_u[NU + 1];
__device__ int   g_off_i[NI + 1];
__device__ int   g_cur_u[NU];
__device__ int   g_cur_i[NI];
__device__ int   g_bsum_u[NBLK];
__device__ int   g_bsum_i[NBLK];
__device__ int2  g_csr_iu[EE];            // edges into user nodes: {src_item, w}
__device__ int2  g_csr_ui[EE];            // edges into item nodes: {src_user, w}
__device__ float g_u1[(size_t)NU * C];    // layer-0 output fp32 (root for layer 1)
__device__ float g_i1[(size_t)NI * C];
__device__ __nv_bfloat162 g_xub[(size_t)NU * C2];  // bf16 gather tables
__device__ __nv_bfloat162 g_xib[(size_t)NI * C2];
__device__ __nv_bfloat162 g_u1b[(size_t)NU * C2];
__device__ __nv_bfloat162 g_i1b[(size_t)NI * C2];

// ---------------------------------------------------------------------------
// fp32 -> bf16 tables, both node types in ONE launch
// ---------------------------------------------------------------------------
__global__ void cvt_both_kernel(const float2* __restrict__ in_u,
                                __nv_bfloat162* __restrict__ out_u,
                                const float2* __restrict__ in_i,
                                __nv_bfloat162* __restrict__ out_i) {
    int i = blockIdx.x * blockDim.x + threadIdx.x;
    if (i < NCV) {
        float2 v = __ldg(in_u + i);
        out_u[i] = __floats2bfloat162_rn(v.x, v.y);
    } else if (i < 2 * NCV) {
        int j = i - NCV;
        float2 v = __ldg(in_i + j);
        out_i[j] = __floats2bfloat162_rn(v.x, v.y);
    }
}

// ---------------------------------------------------------------------------
// in-degree histogram, both edge types in ONE launch
// ---------------------------------------------------------------------------
__global__ void count_both_kernel(const int* __restrict__ dst_u,
                                  const int* __restrict__ dst_i,
                                  int* __restrict__ deg_u,
                                  int* __restrict__ deg_i) {
    int e = blockIdx.x * blockDim.x + threadIdx.x;
    if (e < EE) {
        atomicAdd(&deg_u[__ldg(dst_u + e)], 1);
    } else if (e < 2 * EE) {
        atomicAdd(&deg_i[__ldg(dst_i + (e - EE))], 1);
    }
}

// ---------------------------------------------------------------------------
// exclusive prefix scan, fused over both arrays (blockIdx.y / blockIdx.x)
// ---------------------------------------------------------------------------
__global__ void scan1_kernel(const int* __restrict__ in_u, int* __restrict__ out_u,
                             int* __restrict__ bsum_u,
                             const int* __restrict__ in_i, int* __restrict__ out_i,
                             int* __restrict__ bsum_i) {
    const int* in  = blockIdx.y ? in_i  : in_u;
    int*       out = blockIdx.y ? out_i : out_u;
    int*      bsum = blockIdx.y ? bsum_i : bsum_u;
    const int N = NU;

    __shared__ int sh[SCAN_T];
    int base = blockIdx.x * SCAN_CHUNK + threadIdx.x * SCAN_E;
    int v[SCAN_E];
    int s = 0;
#pragma unroll
    for (int i = 0; i < SCAN_E; i++) {
        int idx = base + i;
        v[i] = (idx < N) ? in[idx] : 0;
        s += v[i];
    }
    sh[threadIdx.x] = s;
    __syncthreads();
    for (int o = 1; o < SCAN_T; o <<= 1) {
        int val = sh[threadIdx.x];
        int add = (threadIdx.x >= o) ? sh[threadIdx.x - o] : 0;
        __syncthreads();
        sh[threadIdx.x] = val + add;
        __syncthreads();
    }
    int run = sh[threadIdx.x] - s;
#pragma unroll
    for (int i = 0; i < SCAN_E; i++) {
        int idx = base + i;
        if (idx < N) out[idx] = run;
        run += v[i];
    }
    if (threadIdx.x == SCAN_T - 1) bsum[blockIdx.x] = sh[SCAN_T - 1];
}

__global__ void scan2_kernel(int* __restrict__ bsum_u, int* __restrict__ bsum_i) {
    int* bsum = blockIdx.x ? bsum_i : bsum_u;
    __shared__ int sh[256];
    int t = threadIdx.x;
    sh[t] = (t < NBLK) ? bsum[t] : 0;
    __syncthreads();
    if (t == 0) {
        int run = 0;
        for (int i = 0; i < NBLK; i++) { int x = sh[i]; sh[i] = run; run += x; }
    }
    __syncthreads();
    if (t < NBLK) bsum[t] = sh[t];
}

// adds block sums, finalizes off[N], and initializes the fill cursors
__global__ void scan3_kernel(int* __restrict__ off_u, const int* __restrict__ bsum_u,
                             int* __restrict__ cur_u,
                             int* __restrict__ off_i, const int* __restrict__ bsum_i,
                             int* __restrict__ cur_i) {
    int*       off  = blockIdx.y ? off_i  : off_u;
    const int* bsum = blockIdx.y ? bsum_i : bsum_u;
    int*       cur  = blockIdx.y ? cur_i  : cur_u;
    const int N = NU;

    int i = blockIdx.x * blockDim.x + threadIdx.x;
    if (i < N) {
        int v = off[i] + bsum[i / SCAN_CHUNK];
        off[i] = v;
        cur[i] = v;
    }
    if (i == 0) off[N] = EE;
}

// ---------------------------------------------------------------------------
// CSR fill, both edge types in ONE launch
// ---------------------------------------------------------------------------
__global__ void fill_both_kernel(const int* __restrict__ ei_iu,
                                 const float* __restrict__ ew_iu,
                                 int* __restrict__ cur_u, int2* __restrict__ csr_iu,
                                 const int* __restrict__ ei_ui,
                                 const float* __restrict__ ew_ui,
                                 int* __restrict__ cur_i, int2* __restrict__ csr_ui) {
    int e = blockIdx.x * blockDim.x + threadIdx.x;
    if (e < EE) {
        int src = __ldg(ei_iu + e);
        int dst = __ldg(ei_iu + EE + e);
        float w = __ldg(ew_iu + e);
        int pos = atomicAdd(&cur_u[dst], 1);
        csr_iu[pos] = make_int2(src, __float_as_int(w));
    } else if (e < 2 * EE) {
        e -= EE;
        int src = __ldg(ei_ui + e);
        int dst = __ldg(ei_ui + EE + e);
        float w = __ldg(ew_ui + e);
        int pos = atomicAdd(&cur_i[dst], 1);
        csr_ui[pos] = make_int2(src, __float_as_int(w));
    }
}

// ---------------------------------------------------------------------------
// fused gather(bf16 src, bit-shift expand) + mean + root(fp32) + LN (+ReLU).
// One warp per dst node; BOTH node types in one launch (warps [0,NU) = user).
// ---------------------------------------------------------------------------
__device__ __forceinline__ void accum_row(float4& acc, const uint2 r, float w) {
    // exact bf16 -> fp32 expansion via bit ops (ALU pipe, not F2F)
    float f0 = __int_as_float(r.x << 16);
    float f1 = __int_as_float(r.x & 0xffff0000u);
    float f2 = __int_as_float(r.y << 16);
    float f3 = __int_as_float(r.y & 0xffff0000u);
    acc.x = fmaf(w, f0, acc.x);
    acc.y = fmaf(w, f1, acc.y);
    acc.z = fmaf(w, f2, acc.z);
    acc.w = fmaf(w, f3, acc.w);
}

__global__ void gather_combine_kernel(
    const int* __restrict__ off_u, const int2* __restrict__ csr_u,
    const uint2* __restrict__ src_u, const float* __restrict__ root_u,
    const float* __restrict__ lnw_u, const float* __restrict__ lnb_u,
    float* __restrict__ outf_u, uint2* __restrict__ outb_u,
    const int* __restrict__ off_i, const int2* __restrict__ csr_i,
    const uint2* __restrict__ src_i, const float* __restrict__ root_i,
    const float* __restrict__ lnw_i, const float* __restrict__ lnb_i,
    float* __restrict__ outf_i, uint2* __restrict__ outb_i,
    int do_relu) {
    int gw   = (blockIdx.x * blockDim.x + threadIdx.x) >> 5;
    int lane = threadIdx.x & 31;
    if (gw >= NU + NI) return;

    const int*   off;  const int2*  csr;  const uint2* src;  const float* root;
    const float* lnw;  const float* lnb;  float* outf;       uint2* outb;
    int node;
    if (gw < NU) {
        node = gw;
        off = off_u; csr = csr_u; src = src_u; root = root_u;
        lnw = lnw_u; lnb = lnb_u; outf = outf_u; outb = outb_u;
    } else {
        node = gw - NU;
        off = off_i; csr = csr_i; src = src_i; root = root_i;
        lnw = lnw_i; lnb = lnb_i; outf = outf_i; outb = outb_i;
    }

    int beg = __ldg(off + node);
    int end = __ldg(off + node + 1);

    float4 acc = make_float4(0.f, 0.f, 0.f, 0.f);
    int e = beg;
    for (; e + 3 < end; e += 4) {
        int2 p0 = __ldg(csr + e);
        int2 p1 = __ldg(csr + e + 1);
        int2 p2 = __ldg(csr + e + 2);
        int2 p3 = __ldg(csr + e + 3);
        uint2 r0 = __ldg(src + (size_t)p0.x * 32 + lane);
        uint2 r1 = __ldg(src + (size_t)p1.x * 32 + lane);
        uint2 r2 = __ldg(src + (size_t)p2.x * 32 + lane);
        uint2 r3 = __ldg(src + (size_t)p3.x * 32 + lane);
        accum_row(acc, r0, __int_as_float(p0.y));
        accum_row(acc, r1, __int_as_float(p1.y));
        accum_row(acc, r2, __int_as_float(p2.y));
        accum_row(acc, r3, __int_as_float(p3.y));
    }
    for (; e < end; e++) {
        int2 p0 = __ldg(csr + e);
        uint2 r0 = __ldg(src + (size_t)p0.x * 32 + lane);
        accum_row(acc, r0, __int_as_float(p0.y));
    }

    float rc = 1.0f / fmaxf((float)(end - beg), 1.0f);

    float4 x = __ldg(reinterpret_cast<const float4*>(root + (size_t)node * C) + lane);
    float4 v;
    v.x = fmaf(acc.x, rc, x.x);
    v.y = fmaf(acc.y, rc, x.y);
    v.z = fmaf(acc.z, rc, x.z);
    v.w = fmaf(acc.w, rc, x.w);

    float m = v.x + v.y + v.z + v.w;
#pragma unroll
    for (int o = 16; o > 0; o >>= 1) m += __shfl_xor_sync(0xffffffffu, m, o);
    m *= (1.0f / C);

    float4 d;
    d.x = v.x - m; d.y = v.y - m; d.z = v.z - m; d.w = v.w - m;

    float var = d.x * d.x + d.y * d.y + d.z * d.z + d.w * d.w;
#pragma unroll
    for (int o = 16; o > 0; o >>= 1) var += __shfl_xor_sync(0xffffffffu, var, o);
    var *= (1.0f / C);

    float inv = rsqrtf(var + LN_EPS);

    float4 wv = __ldg(reinterpret_cast<const float4*>(lnw) + lane);
    float4 bv = __ldg(reinterpret_cast<const float4*>(lnb) + lane);

    float4 o4;
    o4.x = fmaf(d.x * inv, wv.x, bv.x);
    o4.y = fmaf(d.y * inv, wv.y, bv.y);
    o4.z = fmaf(d.z * inv, wv.z, bv.z);
    o4.w = fmaf(d.w * inv, wv.w, bv.w);

    if (do_relu) {
        o4.x = fmaxf(o4.x, 0.0f);
        o4.y = fmaxf(o4.y, 0.0f);
        o4.z = fmaxf(o4.z, 0.0f);
        o4.w = fmaxf(o4.w, 0.0f);
    }

    *(reinterpret_cast<float4*>(outf + (size_t)node * C) + lane) = o4;

    if (outb) {
        uint2 pk;
        __nv_bfloat162 lo = __floats2bfloat162_rn(o4.x, o4.y);
        __nv_bfloat162 hi = __floats2bfloat162_rn(o4.z, o4.w);
        pk.x = *reinterpret_cast<const unsigned int*>(&lo);
        pk.y = *reinterpret_cast<const unsigned int*>(&hi);
        outb[(size_t)node * 32 + lane] = pk;
    }
}

extern "C" void kernel_launch(void* const* d_in, const int* in_sizes, int n_in,
                              void* d_out, int out_size) {
    const float* x_user = (const float*)d_in[0];
    const float* x_item = (const float*)d_in[1];
    const float* ew_ui  = (const float*)d_in[2];
    const float* ew_iu  = (const float*)d_in[3];
    const float* lnwu0  = (const float*)d_in[4];
    const float* lnbu0  = (const float*)d_in[5];
    const float* lnwu1  = (const float*)d_in[6];
    const float* lnbu1  = (const float*)d_in[7];
    const float* lnwi0  = (const float*)d_in[8];
    const float* lnbi0  = (const float*)d_in[9];
    const float* lnwi1  = (const float*)d_in[10];
    const float* lnbi1  = (const float*)d_in[11];
    const int*   ei_ui  = (const int*)d_in[12];
    const int*   ei_iu  = (const int*)d_in[13];
    float*       out    = (float*)d_out;

    int *deg_u, *deg_i, *off_u, *off_i, *cur_u, *cur_i, *bsum_u, *bsum_i;
    int2 *csr_iu, *csr_ui;
    float *u1, *i1;
    __nv_bfloat162 *xub, *xib, *u1b, *i1b;
    cudaGetSymbolAddress((void**)&deg_u, g_deg_u);
    cudaGetSymbolAddress((void**)&deg_i, g_deg_i);
    cudaGetSymbolAddress((void**)&off_u, g_off_u);
    cudaGetSymbolAddress((void**)&off_i, g_off_i);
    cudaGetSymbolAddress((void**)&cur_u, g_cur_u);
    cudaGetSymbolAddress((void**)&cur_i, g_cur_i);
    cudaGetSymbolAddress((void**)&bsum_u, g_bsum_u);
    cudaGetSymbolAddress((void**)&bsum_i, g_bsum_i);
    cudaGetSymbolAddress((void**)&csr_iu, g_csr_iu);
    cudaGetSymbolAddress((void**)&csr_ui, g_csr_ui);
    cudaGetSymbolAddress((void**)&u1, g_u1);
    cudaGetSymbolAddress((void**)&i1, g_i1);
    cudaGetSymbolAddress((void**)&xub, g_xub);
    cudaGetSymbolAddress((void**)&xib, g_xib);
    cudaGetSymbolAddress((void**)&u1b, g_u1b);
    cudaGetSymbolAddress((void**)&i1b, g_i1b);

    // ---- bf16 tables for layer-0 gather sources (one launch) ----
    cvt_both_kernel<<<(2 * NCV + 255) / 256, 256>>>(
        (const float2*)x_user, xub, (const float2*)x_item, xib);

    // ---- CSR build (layer-invariant; fused launches) ----
    cudaMemsetAsync(deg_u, 0, NU * sizeof(int));
    cudaMemsetAsync(deg_i, 0, NI * sizeof(int));
    count_both_kernel<<<(2 * EE + 255) / 256, 256>>>(
        ei_iu + EE, ei_ui + EE, deg_u, deg_i);

    {
        dim3 g1(NBLK, 2);
        scan1_kernel<<<g1, SCAN_T>>>(deg_u, off_u, bsum_u, deg_i, off_i, bsum_i);
        scan2_kernel<<<2, 256>>>(bsum_u, bsum_i);
        dim3 g3((NU + 255) / 256, 2);
        scan3_kernel<<<g3, 256>>>(off_u, bsum_u, cur_u, off_i, bsum_i, cur_i);
    }

    fill_both_kernel<<<(2 * EE + 255) / 256, 256>>>(
        ei_iu, ew_iu, cur_u, csr_iu, ei_ui, ew_ui, cur_i, csr_ui);

    const int GC = (NU + NI) / 8;   // one warp per node, 8 warps/block

    // ---- layer 0 (emit fp32 root + bf16 gather table for layer 1) ----
    gather_combine_kernel<<<GC, 256>>>(
        off_u, csr_iu, (const uint2*)xib, x_user, lnwu0, lnbu0, u1, (uint2*)u1b,
        off_i, csr_ui, (const uint2*)xub, x_item, lnwi0, lnbi0, i1, (uint2*)i1b, 1);

    // ---- layer 1 (final outputs, fp32 only) ----
    gather_combine_kernel<<<GC, 256>>>(
        off_u, csr_iu, (const uint2*)i1b, u1, lnwu1, lnbu1, out, (uint2*)nullptr,
        off_i, csr_ui, (const uint2*)u1b, i1, lnwi1, lnbi1, out + (size_t)NU * C,
        (uint2*)nullptr, 0);
}

// round 5
// speedup vs baseline: 1.0828x; 1.0828x over previous
#include <cuda_runtime.h>
#include <cuda_bf16.h>

#define NU 100000
#define NI 100000
#define EE 1600000
#define C  128
#define C2 (C / 2)          // bfloat162 per row
#define LN_EPS 1e-5f

#define SCAN_T     256
#define SCAN_E     4
#define SCAN_CHUNK (SCAN_T * SCAN_E)   // 1024
#define NB_U ((NU + SCAN_CHUNK - 1) / SCAN_CHUNK)
#define NB_I ((NI + SCAN_CHUNK - 1) / SCAN_CHUNK)

// ---- scratch (allocation-free rule: device globals) ----
__device__ int   g_deg_u[NU];
__device__ int   g_deg_i[NI];
__device__ int   g_off_u[NU + 1];
__device__ int   g_off_i[NI + 1];
__device__ int   g_cur_u[NU];
__device__ int   g_cur_i[NI];
__device__ int   g_bsum_u[NB_U];
__device__ int   g_bsum_i[NB_I];
__device__ int2  g_csr_iu[EE];            // edges into user nodes: {src_item, w}
__device__ int2  g_csr_ui[EE];            // edges into item nodes: {src_user, w}
__device__ float g_u1[(size_t)NU * C];    // layer-0 output fp32 (root for layer 1)
__device__ float g_i1[(size_t)NI * C];
__device__ __nv_bfloat162 g_xub[(size_t)NU * C2];  // bf16 gather tables
__device__ __nv_bfloat162 g_xib[(size_t)NI * C2];
__device__ __nv_bfloat162 g_u1b[(size_t)NU * C2];
__device__ __nv_bfloat162 g_i1b[(size_t)NI * C2];

// ---------------------------------------------------------------------------
// fp32 -> bf16 table conversion (one bfloat162 per thread)
// ---------------------------------------------------------------------------
__global__ void cvt_bf16_kernel(const float2* __restrict__ in,
                                __nv_bfloat162* __restrict__ out, int n2) {
    int i = blockIdx.x * blockDim.x + threadIdx.x;
    if (i < n2) {
        float2 v = __ldg(in + i);
        out[i] = __floats2bfloat162_rn(v.x, v.y);
    }
}

// ---------------------------------------------------------------------------
// in-degree histogram
// ---------------------------------------------------------------------------
__global__ void count_kernel(const int* __restrict__ ei_dst,
                             int* __restrict__ deg, int E) {
    int e = blockIdx.x * blockDim.x + threadIdx.x;
    if (e < E) atomicAdd(&deg[ei_dst[e]], 1);
}

// ---------------------------------------------------------------------------
// exclusive prefix scan (3 kernels)
// ---------------------------------------------------------------------------
__global__ void scan1_kernel(const int* __restrict__ in, int* __restrict__ out,
                             int* __restrict__ bsum, int N) {
    __shared__ int sh[SCAN_T];
    int base = blockIdx.x * SCAN_CHUNK + threadIdx.x * SCAN_E;
    int v[SCAN_E];
    int s = 0;
#pragma unroll
    for (int i = 0; i < SCAN_E; i++) {
        int idx = base + i;
        v[i] = (idx < N) ? in[idx] : 0;
        s += v[i];
    }
    sh[threadIdx.x] = s;
    __syncthreads();
    for (int o = 1; o < SCAN_T; o <<= 1) {
        int val = sh[threadIdx.x];
        int add = (threadIdx.x >= o) ? sh[threadIdx.x - o] : 0;
        __syncthreads();
        sh[threadIdx.x] = val + add;
        __syncthreads();
    }
    int run = sh[threadIdx.x] - s;
#pragma unroll
    for (int i = 0; i < SCAN_E; i++) {
        int idx = base + i;
        if (idx < N) out[idx] = run;
        run += v[i];
    }
    if (threadIdx.x == SCAN_T - 1) bsum[blockIdx.x] = sh[SCAN_T - 1];
}

__global__ void scan2_kernel(int* __restrict__ bsum, int nb) {
    __shared__ int sh[256];
    int t = threadIdx.x;
    sh[t] = (t < nb) ? bsum[t] : 0;
    __syncthreads();
    if (t == 0) {
        int run = 0;
        for (int i = 0; i < nb; i++) { int x = sh[i]; sh[i] = run; run += x; }
    }
    __syncthreads();
    if (t < nb) bsum[t] = sh[t];
}

__global__ void scan3_kernel(int* __restrict__ out, const int* __restrict__ bsum,
                             int N, int total) {
    int i = blockIdx.x * blockDim.x + threadIdx.x;
    if (i < N) out[i] += bsum[i / SCAN_CHUNK];
    if (i == 0) out[N] = total;
}

// ---------------------------------------------------------------------------
// CSR fill: group edges by destination
// ---------------------------------------------------------------------------
__global__ void fill_csr_kernel(const int* __restrict__ ei,
                                const float* __restrict__ ew,
                                int* __restrict__ cursor,
                                int2* __restrict__ csr, int E) {
    int e = blockIdx.x * blockDim.x + threadIdx.x;
    if (e >= E) return;
    int   src = ei[e];
    int   dst = ei[E + e];
    float w   = ew[e];
    int pos = atomicAdd(&cursor[dst], 1);
    csr[pos] = make_int2(src, __float_as_int(w));
}

// ---------------------------------------------------------------------------
// fused gather(bf16 src, exact ALU bit-expansion) + mean + root(fp32) + LN(+ReLU).
// One warp per dst node; lane covers channels [4*lane, 4*lane+3].
// Optionally also emits a bf16 copy (gather source for the next layer).
// ---------------------------------------------------------------------------
__device__ __forceinline__ void accum_row(float4& acc, const uint2 r, float w) {
    // exact bf16 -> fp32 expansion via bit ops (ALU pipe, no F2F)
    float f0 = __int_as_float(r.x << 16);
    float f1 = __int_as_float(r.x & 0xffff0000u);
    float f2 = __int_as_float(r.y << 16);
    float f3 = __int_as_float(r.y & 0xffff0000u);
    acc.x = fmaf(w, f0, acc.x);
    acc.y = fmaf(w, f1, acc.y);
    acc.z = fmaf(w, f2, acc.z);
    acc.w = fmaf(w, f3, acc.w);
}

__global__ void gather_combine_kernel(const int* __restrict__ off,
                                      const int2* __restrict__ csr,
                                      const uint2* __restrict__ xsrc,   // bf16 rows, 32 uint2/row
                                      const float* __restrict__ xdst,   // fp32 rows
                                      const float* __restrict__ lnw,
                                      const float* __restrict__ lnb,
                                      float* __restrict__ out_f,
                                      uint2* __restrict__ out_b,        // may be null
                                      int N, int do_relu) {
    int gw   = (blockIdx.x * blockDim.x + threadIdx.x) >> 5;
    int lane = threadIdx.x & 31;
    if (gw >= N) return;

    int beg = __ldg(off + gw);
    int end = __ldg(off + gw + 1);

    float4 acc = make_float4(0.f, 0.f, 0.f, 0.f);
    int e = beg;
    for (; e + 3 < end; e += 4) {
        int2 p0 = __ldg(csr + e);
        int2 p1 = __ldg(csr + e + 1);
        int2 p2 = __ldg(csr + e + 2);
        int2 p3 = __ldg(csr + e + 3);
        uint2 r0 = __ldg(xsrc + (size_t)p0.x * 32 + lane);
        uint2 r1 = __ldg(xsrc + (size_t)p1.x * 32 + lane);
        uint2 r2 = __ldg(xsrc + (size_t)p2.x * 32 + lane);
        uint2 r3 = __ldg(xsrc + (size_t)p3.x * 32 + lane);
        accum_row(acc, r0, __int_as_float(p0.y));
        accum_row(acc, r1, __int_as_float(p1.y));
        accum_row(acc, r2, __int_as_float(p2.y));
        accum_row(acc, r3, __int_as_float(p3.y));
    }
    for (; e < end; e++) {
        int2 p0 = __ldg(csr + e);
        uint2 r0 = __ldg(xsrc + (size_t)p0.x * 32 + lane);
        accum_row(acc, r0, __int_as_float(p0.y));
    }

    float rc = 1.0f / fmaxf((float)(end - beg), 1.0f);

    float4 x = __ldg(reinterpret_cast<const float4*>(xdst + (size_t)gw * C) + lane);
    float4 v;
    v.x = fmaf(acc.x, rc, x.x);
    v.y = fmaf(acc.y, rc, x.y);
    v.z = fmaf(acc.z, rc, x.z);
    v.w = fmaf(acc.w, rc, x.w);

    float m = v.x + v.y + v.z + v.w;
#pragma unroll
    for (int o = 16; o > 0; o >>= 1) m += __shfl_xor_sync(0xffffffffu, m, o);
    m *= (1.0f / C);

    float4 d;
    d.x = v.x - m; d.y = v.y - m; d.z = v.z - m; d.w = v.w - m;

    float var = d.x * d.x + d.y * d.y + d.z * d.z + d.w * d.w;
#pragma unroll
    for (int o = 16; o > 0; o >>= 1) var += __shfl_xor_sync(0xffffffffu, var, o);
    var *= (1.0f / C);

    float inv = rsqrtf(var + LN_EPS);

    float4 wv = __ldg(reinterpret_cast<const float4*>(lnw) + lane);
    float4 bv = __ldg(reinterpret_cast<const float4*>(lnb) + lane);

    float4 o4;
    o4.x = fmaf(d.x * inv, wv.x, bv.x);
    o4.y = fmaf(d.y * inv, wv.y, bv.y);
    o4.z = fmaf(d.z * inv, wv.z, bv.z);
    o4.w = fmaf(d.w * inv, wv.w, bv.w);

    if (do_relu) {
        o4.x = fmaxf(o4.x, 0.0f);
        o4.y = fmaxf(o4.y, 0.0f);
        o4.z = fmaxf(o4.z, 0.0f);
        o4.w = fmaxf(o4.w, 0.0f);
    }

    *(reinterpret_cast<float4*>(out_f + (size_t)gw * C) + lane) = o4;

    if (out_b) {
        uint2 pk;
        pk.x = (__float_as_uint(o4.y) & 0xffff0000u) | (__float_as_uint(o4.x) >> 16);
        pk.y = (__float_as_uint(o4.w) & 0xffff0000u) | (__float_as_uint(o4.z) >> 16);
        out_b[(size_t)gw * 32 + lane] = pk;
    }
}

extern "C" void kernel_launch(void* const* d_in, const int* in_sizes, int n_in,
                              void* d_out, int out_size) {
    const float* x_user = (const float*)d_in[0];
    const float* x_item = (const float*)d_in[1];
    const float* ew_ui  = (const float*)d_in[2];
    const float* ew_iu  = (const float*)d_in[3];
    const float* lnwu0  = (const float*)d_in[4];
    const float* lnbu0  = (const float*)d_in[5];
    const float* lnwu1  = (const float*)d_in[6];
    const float* lnbu1  = (const float*)d_in[7];
    const float* lnwi0  = (const float*)d_in[8];
    const float* lnbi0  = (const float*)d_in[9];
    const float* lnwi1  = (const float*)d_in[10];
    const float* lnbi1  = (const float*)d_in[11];
    const int*   ei_ui  = (const int*)d_in[12];
    const int*   ei_iu  = (const int*)d_in[13];
    float*       out    = (float*)d_out;

    int *deg_u, *deg_i, *off_u, *off_i, *cur_u, *cur_i, *bsum_u, *bsum_i;
    int2 *csr_iu, *csr_ui;
    float *u1, *i1;
    __nv_bfloat162 *xub, *xib, *u1b, *i1b;
    cudaGetSymbolAddress((void**)&deg_u, g_deg_u);
    cudaGetSymbolAddress((void**)&deg_i, g_deg_i);
    cudaGetSymbolAddress((void**)&off_u, g_off_u);
    cudaGetSymbolAddress((void**)&off_i, g_off_i);
    cudaGetSymbolAddress((void**)&cur_u, g_cur_u);
    cudaGetSymbolAddress((void**)&cur_i, g_cur_i);
    cudaGetSymbolAddress((void**)&bsum_u, g_bsum_u);
    cudaGetSymbolAddress((void**)&bsum_i, g_bsum_i);
    cudaGetSymbolAddress((void**)&csr_iu, g_csr_iu);
    cudaGetSymbolAddress((void**)&csr_ui, g_csr_ui);
    cudaGetSymbolAddress((void**)&u1, g_u1);
    cudaGetSymbolAddress((void**)&i1, g_i1);
    cudaGetSymbolAddress((void**)&xub, g_xub);
    cudaGetSymbolAddress((void**)&xib, g_xib);
    cudaGetSymbolAddress((void**)&u1b, g_u1b);
    cudaGetSymbolAddress((void**)&i1b, g_i1b);

    const int EB   = 256;
    const int EG   = (EE + EB - 1) / EB;
    const int GC_U = NU / 8;     // warp per node, 8 warps/block
    const int GC_I = NI / 8;
    const int NCV  = NU * C2;    // bfloat162 elements per table

    // ---- bf16 tables for layer-0 gather sources ----
    cvt_bf16_kernel<<<(NCV + 255) / 256, 256>>>((const float2*)x_user, xub, NCV);
    cvt_bf16_kernel<<<(NCV + 255) / 256, 256>>>((const float2*)x_item, xib, NCV);

    // ---- CSR build (layer-invariant; reused by both layers) ----
    cudaMemsetAsync(deg_u, 0, NU * sizeof(int));
    cudaMemsetAsync(deg_i, 0, NI * sizeof(int));
    count_kernel<<<EG, EB>>>(ei_iu + EE, deg_u, EE);
    count_kernel<<<EG, EB>>>(ei_ui + EE, deg_i, EE);

    scan1_kernel<<<NB_U, SCAN_T>>>(deg_u, off_u, bsum_u, NU);
    scan2_kernel<<<1, 256>>>(bsum_u, NB_U);
    scan3_kernel<<<(NU + 255) / 256, 256>>>(off_u, bsum_u, NU, EE);

    scan1_kernel<<<NB_I, SCAN_T>>>(deg_i, off_i, bsum_i, NI);
    scan2_kernel<<<1, 256>>>(bsum_i, NB_I);
    scan3_kernel<<<(NI + 255) / 256, 256>>>(off_i, bsum_i, NI, EE);

    cudaMemcpyAsync(cur_u, off_u, NU * sizeof(int), cudaMemcpyDeviceToDevice);
    cudaMemcpyAsync(cur_i, off_i, NI * sizeof(int), cudaMemcpyDeviceToDevice);
    fill_csr_kernel<<<EG, EB>>>(ei_iu, ew_iu, cur_u, csr_iu, EE);
    fill_csr_kernel<<<EG, EB>>>(ei_ui, ew_ui, cur_i, csr_ui, EE);

    // ---- layer 0 (emit fp32 root + bf16 gather table for layer 1) ----
    gather_combine_kernel<<<GC_U, 256>>>(off_u, csr_iu, (const uint2*)xib, x_user,
                                         lnwu0, lnbu0, u1, (uint2*)u1b, NU, 1);
    gather_combine_kernel<<<GC_I, 256>>>(off_i, csr_ui, (const uint2*)xub, x_item,
                                         lnwi0, lnbi0, i1, (uint2*)i1b, NI, 1);

    // ---- layer 1 (final outputs, fp32 only) ----
    gather_combine_kernel<<<GC_U, 256>>>(off_u, csr_iu, (const uint2*)i1b, u1,
                                         lnwu1, lnbu1, out, (uint2*)nullptr, NU, 0);
    gather_combine_kernel<<<GC_I, 256>>>(off_i, csr_ui, (const uint2*)u1b, i1,
                                         lnwi1, lnbi1, out + (size_t)NU * C,
                                         (uint2*)nullptr, NI, 0);
}

// round 6
// speedup vs baseline: 1.1773x; 1.0872x over previous
#include <cuda_runtime.h>
#include <cuda_bf16.h>

#define NU 100000
#define NI 100000
#define EE 1600000
#define C  128
#define LN_EPS 1e-5f

#define SCAN_T     256
#define SCAN_E     4
#define SCAN_CHUNK (SCAN_T * SCAN_E)   // 1024
#define NB_U ((NU + SCAN_CHUNK - 1) / SCAN_CHUNK)
#define NB_I ((NI + SCAN_CHUNK - 1) / SCAN_CHUNK)

// ---- scratch (allocation-free rule: device globals) ----
__device__ int   g_deg_u[NU];
__device__ int   g_deg_i[NI];
__device__ int   g_off_u[NU + 1];
__device__ int   g_off_i[NI + 1];
__device__ int   g_cur_u[NU];
__device__ int   g_cur_i[NI];
__device__ int   g_bsum_u[NB_U];
__device__ int   g_bsum_i[NB_I];
__device__ int2  g_csr_iu[EE];   // edges into user nodes: {src_item*32, w}
__device__ int2  g_csr_ui[EE];   // edges into item nodes: {src_user*32, w}
__device__ float g_u1[(size_t)NU * C];
__device__ float g_i1[(size_t)NI * C];

// ---------------------------------------------------------------------------
// in-degree histogram
// ---------------------------------------------------------------------------
__global__ void count_kernel(const int* __restrict__ ei_dst,
                             int* __restrict__ deg, int E) {
    int e = blockIdx.x * blockDim.x + threadIdx.x;
    if (e < E) atomicAdd(&deg[ei_dst[e]], 1);
}

// ---------------------------------------------------------------------------
// exclusive prefix scan (3 kernels)
// ---------------------------------------------------------------------------
__global__ void scan1_kernel(const int* __restrict__ in, int* __restrict__ out,
                             int* __restrict__ bsum, int N) {
    __shared__ int sh[SCAN_T];
    int base = blockIdx.x * SCAN_CHUNK + threadIdx.x * SCAN_E;
    int v[SCAN_E];
    int s = 0;
#pragma unroll
    for (int i = 0; i < SCAN_E; i++) {
        int idx = base + i;
        v[i] = (idx < N) ? in[idx] : 0;
        s += v[i];
    }
    sh[threadIdx.x] = s;
    __syncthreads();
    for (int o = 1; o < SCAN_T; o <<= 1) {
        int val = sh[threadIdx.x];
        int add = (threadIdx.x >= o) ? sh[threadIdx.x - o] : 0;
        __syncthreads();
        sh[threadIdx.x] = val + add;
        __syncthreads();
    }
    int run = sh[threadIdx.x] - s;
#pragma unroll
    for (int i = 0; i < SCAN_E; i++) {
        int idx = base + i;
        if (idx < N) out[idx] = run;
        run += v[i];
    }
    if (threadIdx.x == SCAN_T - 1) bsum[blockIdx.x] = sh[SCAN_T - 1];
}

__global__ void scan2_kernel(int* __restrict__ bsum, int nb) {
    __shared__ int sh[256];
    int t = threadIdx.x;
    sh[t] = (t < nb) ? bsum[t] : 0;
    __syncthreads();
    if (t == 0) {
        int run = 0;
        for (int i = 0; i < nb; i++) { int x = sh[i]; sh[i] = run; run += x; }
    }
    __syncthreads();
    if (t < nb) bsum[t] = sh[t];
}

// adds block sums, finalizes off[N], and initializes the fill cursor
__global__ void scan3_kernel(int* __restrict__ out, const int* __restrict__ bsum,
                             int* __restrict__ cur, int N, int total) {
    int i = blockIdx.x * blockDim.x + threadIdx.x;
    if (i < N) {
        int v = out[i] + bsum[i / SCAN_CHUNK];
        out[i] = v;
        cur[i] = v;
    }
    if (i == 0) out[N] = total;
}

// ---------------------------------------------------------------------------
// CSR fill: group edges by destination; store src pre-scaled by 32 (float4
// row stride) so the gather inner loop does pure pointer+lane addressing.
// ---------------------------------------------------------------------------
__global__ void fill_csr_kernel(const int* __restrict__ ei,
                                const float* __restrict__ ew,
                                int* __restrict__ cursor,
                                int2* __restrict__ csr, int E) {
    int e = blockIdx.x * blockDim.x + threadIdx.x;
    if (e >= E) return;
    int   src = ei[e];
    int   dst = ei[E + e];
    float w   = ew[e];
    int pos = atomicAdd(&cursor[dst], 1);
    csr[pos] = make_int2(src * 32, __float_as_int(w));
}

// ---------------------------------------------------------------------------
// fused gather + mean + root + LayerNorm (+ReLU). One warp per dst node.
// ---------------------------------------------------------------------------
__global__ void __launch_bounds__(256)
gather_combine_kernel(const int* __restrict__ off,
                      const int2* __restrict__ csr,
                      const float4* __restrict__ xsrc,   // 32 float4 per row
                      const float* __restrict__ xdst,
                      const float* __restrict__ lnw,
                      const float* __restrict__ lnb,
                      float* __restrict__ out, int N, int do_relu) {
    int gw   = (blockIdx.x * blockDim.x + threadIdx.x) >> 5;
    int lane = threadIdx.x & 31;
    if (gw >= N) return;

    int beg = __ldg(off + gw);
    int end = __ldg(off + gw + 1);

    float4 acc = make_float4(0.f, 0.f, 0.f, 0.f);
    int e = beg;
    for (; e + 3 < end; e += 4) {
        int2 p0 = __ldg(csr + e);
        int2 p1 = __ldg(csr + e + 1);
        int2 p2 = __ldg(csr + e + 2);
        int2 p3 = __ldg(csr + e + 3);
        float4 v0 = __ldg(xsrc + p0.x + lane);
        float4 v1 = __ldg(xsrc + p1.x + lane);
        float4 v2 = __ldg(xsrc + p2.x + lane);
        float4 v3 = __ldg(xsrc + p3.x + lane);
        float w0 = __int_as_float(p0.y);
        float w1 = __int_as_float(p1.y);
        float w2 = __int_as_float(p2.y);
        float w3 = __int_as_float(p3.y);
        acc.x = fmaf(w0, v0.x, acc.x); acc.y = fmaf(w0, v0.y, acc.y);
        acc.z = fmaf(w0, v0.z, acc.z); acc.w = fmaf(w0, v0.w, acc.w);
        acc.x = fmaf(w1, v1.x, acc.x); acc.y = fmaf(w1, v1.y, acc.y);
        acc.z = fmaf(w1, v1.z, acc.z); acc.w = fmaf(w1, v1.w, acc.w);
        acc.x = fmaf(w2, v2.x, acc.x); acc.y = fmaf(w2, v2.y, acc.y);
        acc.z = fmaf(w2, v2.z, acc.z); acc.w = fmaf(w2, v2.w, acc.w);
        acc.x = fmaf(w3, v3.x, acc.x); acc.y = fmaf(w3, v3.y, acc.y);
        acc.z = fmaf(w3, v3.z, acc.z); acc.w = fmaf(w3, v3.w, acc.w);
    }
    for (; e < end; e++) {
        int2 p0 = __ldg(csr + e);
        float4 v0 = __ldg(xsrc + p0.x + lane);
        float w0 = __int_as_float(p0.y);
        acc.x = fmaf(w0, v0.x, acc.x); acc.y = fmaf(w0, v0.y, acc.y);
        acc.z = fmaf(w0, v0.z, acc.z); acc.w = fmaf(w0, v0.w, acc.w);
    }

    float rc = 1.0f / fmaxf((float)(end - beg), 1.0f);

    float4 x = __ldg(reinterpret_cast<const float4*>(xdst + (size_t)gw * C) + lane);
    float4 v;
    v.x = fmaf(acc.x, rc, x.x);
    v.y = fmaf(acc.y, rc, x.y);
    v.z = fmaf(acc.z, rc, x.z);
    v.w = fmaf(acc.w, rc, x.w);

    float m = v.x + v.y + v.z + v.w;
#pragma unroll
    for (int o = 16; o > 0; o >>= 1) m += __shfl_xor_sync(0xffffffffu, m, o);
    m *= (1.0f / C);

    float4 d;
    d.x = v.x - m; d.y = v.y - m; d.z = v.z - m; d.w = v.w - m;

    float var = d.x * d.x + d.y * d.y + d.z * d.z + d.w * d.w;
#pragma unroll
    for (int o = 16; o > 0; o >>= 1) var += __shfl_xor_sync(0xffffffffu, var, o);
    var *= (1.0f / C);

    float inv = rsqrtf(var + LN_EPS);

    float4 wv = __ldg(reinterpret_cast<const float4*>(lnw) + lane);
    float4 bv = __ldg(reinterpret_cast<const float4*>(lnb) + lane);

    float4 o4;
    o4.x = fmaf(d.x * inv, wv.x, bv.x);
    o4.y = fmaf(d.y * inv, wv.y, bv.y);
    o4.z = fmaf(d.z * inv, wv.z, bv.z);
    o4.w = fmaf(d.w * inv, wv.w, bv.w);

    if (do_relu) {
        o4.x = fmaxf(o4.x, 0.0f);
        o4.y = fmaxf(o4.y, 0.0f);
        o4.z = fmaxf(o4.z, 0.0f);
        o4.w = fmaxf(o4.w, 0.0f);
    }

    *(reinterpret_cast<float4*>(out + (size_t)gw * C) + lane) = o4;
}

extern "C" void kernel_launch(void* const* d_in, const int* in_sizes, int n_in,
                              void* d_out, int out_size) {
    const float* x_user = (const float*)d_in[0];
    const float* x_item = (const float*)d_in[1];
    const float* ew_ui  = (const float*)d_in[2];
    const float* ew_iu  = (const float*)d_in[3];
    const float* lnwu0  = (const float*)d_in[4];
    const float* lnbu0  = (const float*)d_in[5];
    const float* lnwu1  = (const float*)d_in[6];
    const float* lnbu1  = (const float*)d_in[7];
    const float* lnwi0  = (const float*)d_in[8];
    const float* lnbi0  = (const float*)d_in[9];
    const float* lnwi1  = (const float*)d_in[10];
    const float* lnbi1  = (const float*)d_in[11];
    const int*   ei_ui  = (const int*)d_in[12];
    const int*   ei_iu  = (const int*)d_in[13];
    float*       out    = (float*)d_out;

    int *deg_u, *deg_i, *off_u, *off_i, *cur_u, *cur_i, *bsum_u, *bsum_i;
    int2 *csr_iu, *csr_ui;
    float *u1, *i1;
    cudaGetSymbolAddress((void**)&deg_u, g_deg_u);
    cudaGetSymbolAddress((void**)&deg_i, g_deg_i);
    cudaGetSymbolAddress((void**)&off_u, g_off_u);
    cudaGetSymbolAddress((void**)&off_i, g_off_i);
    cudaGetSymbolAddress((void**)&cur_u, g_cur_u);
    cudaGetSymbolAddress((void**)&cur_i, g_cur_i);
    cudaGetSymbolAddress((void**)&bsum_u, g_bsum_u);
    cudaGetSymbolAddress((void**)&bsum_i, g_bsum_i);
    cudaGetSymbolAddress((void**)&csr_iu, g_csr_iu);
    cudaGetSymbolAddress((void**)&csr_ui, g_csr_ui);
    cudaGetSymbolAddress((void**)&u1, g_u1);
    cudaGetSymbolAddress((void**)&i1, g_i1);

    const int EB   = 256;
    const int EG   = (EE + EB - 1) / EB;
    const int GC_U = NU / 8;     // warp per node, 8 warps/block
    const int GC_I = NI / 8;

    // ---- CSR build (layer-invariant; reused by both layers) ----
    cudaMemsetAsync(deg_u, 0, NU * sizeof(int));
    cudaMemsetAsync(deg_i, 0, NI * sizeof(int));
    count_kernel<<<EG, EB>>>(ei_iu + EE, deg_u, EE);
    count_kernel<<<EG, EB>>>(ei_ui + EE, deg_i, EE);

    scan1_kernel<<<NB_U, SCAN_T>>>(deg_u, off_u, bsum_u, NU);
    scan2_kernel<<<1, 256>>>(bsum_u, NB_U);
    scan3_kernel<<<(NU + 255) / 256, 256>>>(off_u, bsum_u, cur_u, NU, EE);

    scan1_kernel<<<NB_I, SCAN_T>>>(deg_i, off_i, bsum_i, NI);
    scan2_kernel<<<1, 256>>>(bsum_i, NB_I);
    scan3_kernel<<<(NI + 255) / 256, 256>>>(off_i, bsum_i, cur_i, NI, EE);

    fill_csr_kernel<<<EG, EB>>>(ei_iu, ew_iu, cur_u, csr_iu, EE);
    fill_csr_kernel<<<EG, EB>>>(ei_ui, ew_ui, cur_i, csr_ui, EE);

    // ---- layer 0 ----
    gather_combine_kernel<<<GC_U, 256>>>(off_u, csr_iu, (const float4*)x_item,
                                         x_user, lnwu0, lnbu0, u1, NU, 1);
    gather_combine_kernel<<<GC_I, 256>>>(off_i, csr_ui, (const float4*)x_user,
                                         x_item, lnwi0, lnbi0, i1, NI, 1);

    // ---- layer 1 ----
    gather_combine_kernel<<<GC_U, 256>>>(off_u, csr_iu, (const float4*)i1,
                                         u1, lnwu1, lnbu1, out, NU, 0);
    gather_combine_kernel<<<GC_I, 256>>>(off_i, csr_ui, (const float4*)u1,
                                         i1, lnwi1, lnbi1, out + (size_t)NU * C,
                                         NI, 0);
}

// round 7
// speedup vs baseline: 1.3110x; 1.1136x over previous
#include <cuda_runtime.h>
#include <cuda_bf16.h>

#define NU 100000
#define NI 100000
#define EE 1600000
#define C  128
#define LN_EPS 1e-5f

#define SCAN_T     256
#define SCAN_E     4
#define SCAN_CHUNK (SCAN_T * SCAN_E)   // 1024
#define NBLK ((NU + SCAN_CHUNK - 1) / SCAN_CHUNK)   // 98 (NU == NI)

// ---- scratch (allocation-free rule: device globals) ----
__device__ int   g_deg_u[NU];
__device__ int   g_deg_i[NI];
__device__ int   g_off_u[NU + 1];
__device__ int   g_off_i[NI + 1];
__device__ int   g_cur_u[NU];
__device__ int   g_cur_i[NI];
__device__ int   g_bsum_u[NBLK];
__device__ int   g_bsum_i[NBLK];
__device__ int2  g_csr_iu[EE];   // edges into user nodes: {src_item, w}
__device__ int2  g_csr_ui[EE];   // edges into item nodes: {src_user, w}
__device__ float g_u1[(size_t)NU * C];
__device__ float g_i1[(size_t)NI * C];

// ---------------------------------------------------------------------------
// in-degree histogram, both edge types in one launch (independent arrays)
// ---------------------------------------------------------------------------
__global__ void count_both_kernel(const int* __restrict__ dst_u,
                                  const int* __restrict__ dst_i,
                                  int* __restrict__ deg_u,
                                  int* __restrict__ deg_i) {
    int e = blockIdx.x * blockDim.x + threadIdx.x;
    if (e < EE) {
        atomicAdd(&deg_u[__ldg(dst_u + e)], 1);
    } else if (e < 2 * EE) {
        atomicAdd(&deg_i[__ldg(dst_i + (e - EE))], 1);
    }
}

// ---------------------------------------------------------------------------
// exclusive prefix scan, u/i pairs fused via blockIdx.y / blockIdx.x
// ---------------------------------------------------------------------------
__global__ void scan1_kernel(const int* __restrict__ in_u, int* __restrict__ out_u,
                             int* __restrict__ bsum_u,
                             const int* __restrict__ in_i, int* __restrict__ out_i,
                             int* __restrict__ bsum_i) {
    const int* in  = blockIdx.y ? in_i  : in_u;
    int*       out = blockIdx.y ? out_i : out_u;
    int*      bsum = blockIdx.y ? bsum_i : bsum_u;
    const int N = NU;

    __shared__ int sh[SCAN_T];
    int base = blockIdx.x * SCAN_CHUNK + threadIdx.x * SCAN_E;
    int v[SCAN_E];
    int s = 0;
#pragma unroll
    for (int i = 0; i < SCAN_E; i++) {
        int idx = base + i;
        v[i] = (idx < N) ? in[idx] : 0;
        s += v[i];
    }
    sh[threadIdx.x] = s;
    __syncthreads();
    for (int o = 1; o < SCAN_T; o <<= 1) {
        int val = sh[threadIdx.x];
        int add = (threadIdx.x >= o) ? sh[threadIdx.x - o] : 0;
        __syncthreads();
        sh[threadIdx.x] = val + add;
        __syncthreads();
    }
    int run = sh[threadIdx.x] - s;
#pragma unroll
    for (int i = 0; i < SCAN_E; i++) {
        int idx = base + i;
        if (idx < N) out[idx] = run;
        run += v[i];
    }
    if (threadIdx.x == SCAN_T - 1) bsum[blockIdx.x] = sh[SCAN_T - 1];
}

__global__ void scan2_kernel(int* __restrict__ bsum_u, int* __restrict__ bsum_i) {
    int* bsum = blockIdx.x ? bsum_i : bsum_u;
    __shared__ int sh[256];
    int t = threadIdx.x;
    sh[t] = (t < NBLK) ? bsum[t] : 0;
    __syncthreads();
    if (t == 0) {
        int run = 0;
        for (int i = 0; i < NBLK; i++) { int x = sh[i]; sh[i] = run; run += x; }
    }
    __syncthreads();
    if (t < NBLK) bsum[t] = sh[t];
}

// adds block sums, finalizes off[N], and initializes the fill cursors
__global__ void scan3_kernel(int* __restrict__ off_u, const int* __restrict__ bsum_u,
                             int* __restrict__ cur_u,
                             int* __restrict__ off_i, const int* __restrict__ bsum_i,
                             int* __restrict__ cur_i) {
    int*       off  = blockIdx.y ? off_i  : off_u;
    const int* bsum = blockIdx.y ? bsum_i : bsum_u;
    int*       cur  = blockIdx.y ? cur_i  : cur_u;
    const int N = NU;

    int i = blockIdx.x * blockDim.x + threadIdx.x;
    if (i < N) {
        int v = off[i] + bsum[i / SCAN_CHUNK];
        off[i] = v;
        cur[i] = v;
    }
    if (i == 0) off[N] = EE;
}

// ---------------------------------------------------------------------------
// CSR fill, both edge types in one launch (independent arrays)
// ---------------------------------------------------------------------------
__global__ void fill_both_kernel(const int* __restrict__ ei_iu,
                                 const float* __restrict__ ew_iu,
                                 int* __restrict__ cur_u, int2* __restrict__ csr_iu,
                                 const int* __restrict__ ei_ui,
                                 const float* __restrict__ ew_ui,
                                 int* __restrict__ cur_i, int2* __restrict__ csr_ui) {
    int e = blockIdx.x * blockDim.x + threadIdx.x;
    if (e < EE) {
        int src = __ldg(ei_iu + e);
        int dst = __ldg(ei_iu + EE + e);
        float w = __ldg(ew_iu + e);
        int pos = atomicAdd(&cur_u[dst], 1);
        csr_iu[pos] = make_int2(src, __float_as_int(w));
    } else if (e < 2 * EE) {
        e -= EE;
        int src = __ldg(ei_ui + e);
        int dst = __ldg(ei_ui + EE + e);
        float w = __ldg(ew_ui + e);
        int pos = atomicAdd(&cur_i[dst], 1);
        csr_ui[pos] = make_int2(src, __float_as_int(w));
    }
}

// ---------------------------------------------------------------------------
// fused gather + mean + root + LayerNorm (+ReLU). One warp per dst node.
// EXACT R2 body (unroll 2) — empirically optimal; do not change.
// ---------------------------------------------------------------------------
__global__ void gather_combine_kernel(const int* __restrict__ off,
                                      const int2* __restrict__ csr,
                                      const float* __restrict__ xsrc,
                                      const float* __restrict__ xdst,
                                      const float* __restrict__ lnw,
                                      const float* __restrict__ lnb,
                                      float* __restrict__ out,
                                      int N, int do_relu) {
    int gw   = (blockIdx.x * blockDim.x + threadIdx.x) >> 5;
    int lane = threadIdx.x & 31;
    if (gw >= N) return;

    int beg = __ldg(off + gw);
    int end = __ldg(off + gw + 1);

    float4 acc = make_float4(0.f, 0.f, 0.f, 0.f);
    int e = beg;
    for (; e + 1 < end; e += 2) {
        int2 p0 = __ldg(csr + e);
        int2 p1 = __ldg(csr + e + 1);
        float4 v0 = __ldg(reinterpret_cast<const float4*>(xsrc + (size_t)p0.x * C) + lane);
        float4 v1 = __ldg(reinterpret_cast<const float4*>(xsrc + (size_t)p1.x * C) + lane);
        float w0 = __int_as_float(p0.y);
        float w1 = __int_as_float(p1.y);
        acc.x = fmaf(w0, v0.x, acc.x); acc.y = fmaf(w0, v0.y, acc.y);
        acc.z = fmaf(w0, v0.z, acc.z); acc.w = fmaf(w0, v0.w, acc.w);
        acc.x = fmaf(w1, v1.x, acc.x); acc.y = fmaf(w1, v1.y, acc.y);
        acc.z = fmaf(w1, v1.z, acc.z); acc.w = fmaf(w1, v1.w, acc.w);
    }
    if (e < end) {
        int2 p0 = __ldg(csr + e);
        float4 v0 = __ldg(reinterpret_cast<const float4*>(xsrc + (size_t)p0.x * C) + lane);
        float w0 = __int_as_float(p0.y);
        acc.x = fmaf(w0, v0.x, acc.x); acc.y = fmaf(w0, v0.y, acc.y);
        acc.z = fmaf(w0, v0.z, acc.z); acc.w = fmaf(w0, v0.w, acc.w);
    }

    float rc = 1.0f / fmaxf((float)(end - beg), 1.0f);

    float4 x = __ldg(reinterpret_cast<const float4*>(xdst + (size_t)gw * C) + lane);
    float4 v;
    v.x = fmaf(acc.x, rc, x.x);
    v.y = fmaf(acc.y, rc, x.y);
    v.z = fmaf(acc.z, rc, x.z);
    v.w = fmaf(acc.w, rc, x.w);

    float m = v.x + v.y + v.z + v.w;
#pragma unroll
    for (int o = 16; o > 0; o >>= 1) m += __shfl_xor_sync(0xffffffffu, m, o);
    m *= (1.0f / C);

    float4 d;
    d.x = v.x - m; d.y = v.y - m; d.z = v.z - m; d.w = v.w - m;

    float var = d.x * d.x + d.y * d.y + d.z * d.z + d.w * d.w;
#pragma unroll
    for (int o = 16; o > 0; o >>= 1) var += __shfl_xor_sync(0xffffffffu, var, o);
    var *= (1.0f / C);

    float inv = rsqrtf(var + LN_EPS);

    float4 wv = __ldg(reinterpret_cast<const float4*>(lnw) + lane);
    float4 bv = __ldg(reinterpret_cast<const float4*>(lnb) + lane);

    float4 o4;
    o4.x = fmaf(d.x * inv, wv.x, bv.x);
    o4.y = fmaf(d.y * inv, wv.y, bv.y);
    o4.z = fmaf(d.z * inv, wv.z, bv.z);
    o4.w = fmaf(d.w * inv, wv.w, bv.w);

    if (do_relu) {
        o4.x = fmaxf(o4.x, 0.0f);
        o4.y = fmaxf(o4.y, 0.0f);
        o4.z = fmaxf(o4.z, 0.0f);
        o4.w = fmaxf(o4.w, 0.0f);
    }

    *(reinterpret_cast<float4*>(out + (size_t)gw * C) + lane) = o4;
}

extern "C" void kernel_launch(void* const* d_in, const int* in_sizes, int n_in,
                              void* d_out, int out_size) {
    const float* x_user = (const float*)d_in[0];
    const float* x_item = (const float*)d_in[1];
    const float* ew_ui  = (const float*)d_in[2];
    const float* ew_iu  = (const float*)d_in[3];
    const float* lnwu0  = (const float*)d_in[4];
    const float* lnbu0  = (const float*)d_in[5];
    const float* lnwu1  = (const float*)d_in[6];
    const float* lnbu1  = (const float*)d_in[7];
    const float* lnwi0  = (const float*)d_in[8];
    const float* lnbi0  = (const float*)d_in[9];
    const float* lnwi1  = (const float*)d_in[10];
    const float* lnbi1  = (const float*)d_in[11];
    const int*   ei_ui  = (const int*)d_in[12];
    const int*   ei_iu  = (const int*)d_in[13];
    float*       out    = (float*)d_out;

    int *deg_u, *deg_i, *off_u, *off_i, *cur_u, *cur_i, *bsum_u, *bsum_i;
    int2 *csr_iu, *csr_ui;
    float *u1, *i1;
    cudaGetSymbolAddress((void**)&deg_u, g_deg_u);
    cudaGetSymbolAddress((void**)&deg_i, g_deg_i);
    cudaGetSymbolAddress((void**)&off_u, g_off_u);
    cudaGetSymbolAddress((void**)&off_i, g_off_i);
    cudaGetSymbolAddress((void**)&cur_u, g_cur_u);
    cudaGetSymbolAddress((void**)&cur_i, g_cur_i);
    cudaGetSymbolAddress((void**)&bsum_u, g_bsum_u);
    cudaGetSymbolAddress((void**)&bsum_i, g_bsum_i);
    cudaGetSymbolAddress((void**)&csr_iu, g_csr_iu);
    cudaGetSymbolAddress((void**)&csr_ui, g_csr_ui);
    cudaGetSymbolAddress((void**)&u1, g_u1);
    cudaGetSymbolAddress((void**)&i1, g_i1);

    const int GC_U = NU / 8;     // warp per node, 8 warps/block
    const int GC_I = NI / 8;

    // ---- CSR build (layer-invariant; u/i pairs run concurrently) ----
    cudaMemsetAsync(deg_u, 0, NU * sizeof(int));
    cudaMemsetAsync(deg_i, 0, NI * sizeof(int));
    count_both_kernel<<<(2 * EE + 255) / 256, 256>>>(
        ei_iu + EE, ei_ui + EE, deg_u, deg_i);

    {
        dim3 g1(NBLK, 2);
        scan1_kernel<<<g1, SCAN_T>>>(deg_u, off_u, bsum_u, deg_i, off_i, bsum_i);
        scan2_kernel<<<2, 256>>>(bsum_u, bsum_i);
        dim3 g3((NU + 255) / 256, 2);
        scan3_kernel<<<g3, 256>>>(off_u, bsum_u, cur_u, off_i, bsum_i, cur_i);
    }

    fill_both_kernel<<<(2 * EE + 255) / 256, 256>>>(
        ei_iu, ew_iu, cur_u, csr_iu, ei_ui, ew_ui, cur_i, csr_ui);

    // ---- layer 0 ----
    gather_combine_kernel<<<GC_U, 256>>>(off_u, csr_iu, x_item, x_user,
                                         lnwu0, lnbu0, u1, NU, 1);
    gather_combine_kernel<<<GC_I, 256>>>(off_i, csr_ui, x_user, x_item,
                                         lnwi0, lnbi0, i1, NI, 1);

    // ---- layer 1 ----
    gather_combine_kernel<<<GC_U, 256>>>(off_u, csr_iu, i1, u1,
                                         lnwu1, lnbu1, out, NU, 0);
    gather_combine_kernel<<<GC_I, 256>>>(off_i, csr_ui, u1, i1,
                                         lnwi1, lnbi1, out + (size_t)NU * C, NI, 0);
}

// round 8
// speedup vs baseline: 1.3210x; 1.0076x over previous
#include <cuda_runtime.h>
#include <cuda_bf16.h>

#define NU 100000
#define NI 100000
#define EE 1600000
#define C  128
#define LN_EPS 1e-5f

#define SCAN_T     256
#define SCAN_E     4
#define SCAN_CHUNK (SCAN_T * SCAN_E)   // 1024
#define NBLK ((NU + SCAN_CHUNK - 1) / SCAN_CHUNK)   // 98 (NU == NI)

// ---- scratch (allocation-free rule: device globals) ----
__device__ int   g_deg[2 * NU];          // [0,NU)=user, [NU,2NU)=item
__device__ int   g_off_u[NU + 1];
__device__ int   g_off_i[NI + 1];
__device__ int   g_cur_u[NU];
__device__ int   g_cur_i[NI];
__device__ int   g_bsum_u[NBLK];
__device__ int   g_bsum_i[NBLK];
__device__ int2  g_csr_iu[EE];   // edges into user nodes: {src_item, w}
__device__ int2  g_csr_ui[EE];   // edges into item nodes: {src_user, w}
__device__ float g_u1[(size_t)NU * C];
__device__ float g_i1[(size_t)NI * C];

// ---------------------------------------------------------------------------
// in-degree histogram, both edge types in one launch (independent arrays)
// ---------------------------------------------------------------------------
__global__ void count_both_kernel(const int* __restrict__ dst_u,
                                  const int* __restrict__ dst_i,
                                  int* __restrict__ deg_u,
                                  int* __restrict__ deg_i) {
    int e = blockIdx.x * blockDim.x + threadIdx.x;
    if (e < EE) {
        atomicAdd(&deg_u[__ldg(dst_u + e)], 1);
    } else if (e < 2 * EE) {
        atomicAdd(&deg_i[__ldg(dst_i + (e - EE))], 1);
    }
}

// ---------------------------------------------------------------------------
// exclusive prefix scan, u/i pairs fused via blockIdx.y / blockIdx.x
// ---------------------------------------------------------------------------
__global__ void scan1_kernel(const int* __restrict__ in_u, int* __restrict__ out_u,
                             int* __restrict__ bsum_u,
                             const int* __restrict__ in_i, int* __restrict__ out_i,
                             int* __restrict__ bsum_i) {
    const int* in  = blockIdx.y ? in_i  : in_u;
    int*       out = blockIdx.y ? out_i : out_u;
    int*      bsum = blockIdx.y ? bsum_i : bsum_u;
    const int N = NU;

    __shared__ int sh[SCAN_T];
    int base = blockIdx.x * SCAN_CHUNK + threadIdx.x * SCAN_E;
    int v[SCAN_E];
    int s = 0;
#pragma unroll
    for (int i = 0; i < SCAN_E; i++) {
        int idx = base + i;
        v[i] = (idx < N) ? in[idx] : 0;
        s += v[i];
    }
    sh[threadIdx.x] = s;
    __syncthreads();
    for (int o = 1; o < SCAN_T; o <<= 1) {
        int val = sh[threadIdx.x];
        int add = (threadIdx.x >= o) ? sh[threadIdx.x - o] : 0;
        __syncthreads();
        sh[threadIdx.x] = val + add;
        __syncthreads();
    }
    int run = sh[threadIdx.x] - s;
#pragma unroll
    for (int i = 0; i < SCAN_E; i++) {
        int idx = base + i;
        if (idx < N) out[idx] = run;
        run += v[i];
    }
    if (threadIdx.x == SCAN_T - 1) bsum[blockIdx.x] = sh[SCAN_T - 1];
}

__global__ void scan2_kernel(int* __restrict__ bsum_u, int* __restrict__ bsum_i) {
    int* bsum = blockIdx.x ? bsum_i : bsum_u;
    __shared__ int sh[256];
    int t = threadIdx.x;
    sh[t] = (t < NBLK) ? bsum[t] : 0;
    __syncthreads();
    if (t == 0) {
        int run = 0;
        for (int i = 0; i < NBLK; i++) { int x = sh[i]; sh[i] = run; run += x; }
    }
    __syncthreads();
    if (t < NBLK) bsum[t] = sh[t];
}

// adds block sums, finalizes off[N], and initializes the fill cursors
__global__ void scan3_kernel(int* __restrict__ off_u, const int* __restrict__ bsum_u,
                             int* __restrict__ cur_u,
                             int* __restrict__ off_i, const int* __restrict__ bsum_i,
                             int* __restrict__ cur_i) {
    int*       off  = blockIdx.y ? off_i  : off_u;
    const int* bsum = blockIdx.y ? bsum_i : bsum_u;
    int*       cur  = blockIdx.y ? cur_i  : cur_u;
    const int N = NU;

    int i = blockIdx.x * blockDim.x + threadIdx.x;
    if (i < N) {
        int v = off[i] + bsum[i / SCAN_CHUNK];
        off[i] = v;
        cur[i] = v;
    }
    if (i == 0) off[N] = EE;
}

// ---------------------------------------------------------------------------
// CSR fill, both edge types in one launch (independent arrays)
// ---------------------------------------------------------------------------
__global__ void fill_both_kernel(const int* __restrict__ ei_iu,
                                 const float* __restrict__ ew_iu,
                                 int* __restrict__ cur_u, int2* __restrict__ csr_iu,
                                 const int* __restrict__ ei_ui,
                                 const float* __restrict__ ew_ui,
                                 int* __restrict__ cur_i, int2* __restrict__ csr_ui) {
    int e = blockIdx.x * blockDim.x + threadIdx.x;
    if (e < EE) {
        int src = __ldg(ei_iu + e);
        int dst = __ldg(ei_iu + EE + e);
        float w = __ldg(ew_iu + e);
        int pos = atomicAdd(&cur_u[dst], 1);
        csr_iu[pos] = make_int2(src, __float_as_int(w));
    } else if (e < 2 * EE) {
        e -= EE;
        int src = __ldg(ei_ui + e);
        int dst = __ldg(ei_ui + EE + e);
        float w = __ldg(ew_ui + e);
        int pos = atomicAdd(&cur_i[dst], 1);
        csr_ui[pos] = make_int2(src, __float_as_int(w));
    }
}

// ---------------------------------------------------------------------------
// fused gather + mean + root + LayerNorm (+ReLU). One warp per dst node.
// EXACT R2 body (unroll 2) — empirically optimal; do not change.
// stream_out: final-layer outputs are never re-read -> evict-first stores.
// ---------------------------------------------------------------------------
__global__ void gather_combine_kernel(const int* __restrict__ off,
                                      const int2* __restrict__ csr,
                                      const float* __restrict__ xsrc,
                                      const float* __restrict__ xdst,
                                      const float* __restrict__ lnw,
                                      const float* __restrict__ lnb,
                                      float* __restrict__ out,
                                      int N, int do_relu, int stream_out) {
    int gw   = (blockIdx.x * blockDim.x + threadIdx.x) >> 5;
    int lane = threadIdx.x & 31;
    if (gw >= N) return;

    int beg = __ldg(off + gw);
    int end = __ldg(off + gw + 1);

    float4 acc = make_float4(0.f, 0.f, 0.f, 0.f);
    int e = beg;
    for (; e + 1 < end; e += 2) {
        int2 p0 = __ldg(csr + e);
        int2 p1 = __ldg(csr + e + 1);
        float4 v0 = __ldg(reinterpret_cast<const float4*>(xsrc + (size_t)p0.x * C) + lane);
        float4 v1 = __ldg(reinterpret_cast<const float4*>(xsrc + (size_t)p1.x * C) + lane);
        float w0 = __int_as_float(p0.y);
        float w1 = __int_as_float(p1.y);
        acc.x = fmaf(w0, v0.x, acc.x); acc.y = fmaf(w0, v0.y, acc.y);
        acc.z = fmaf(w0, v0.z, acc.z); acc.w = fmaf(w0, v0.w, acc.w);
        acc.x = fmaf(w1, v1.x, acc.x); acc.y = fmaf(w1, v1.y, acc.y);
        acc.z = fmaf(w1, v1.z, acc.z); acc.w = fmaf(w1, v1.w, acc.w);
    }
    if (e < end) {
        int2 p0 = __ldg(csr + e);
        float4 v0 = __ldg(reinterpret_cast<const float4*>(xsrc + (size_t)p0.x * C) + lane);
        float w0 = __int_as_float(p0.y);
        acc.x = fmaf(w0, v0.x, acc.x); acc.y = fmaf(w0, v0.y, acc.y);
        acc.z = fmaf(w0, v0.z, acc.z); acc.w = fmaf(w0, v0.w, acc.w);
    }

    float rc = 1.0f / fmaxf((float)(end - beg), 1.0f);

    float4 x = __ldg(reinterpret_cast<const float4*>(xdst + (size_t)gw * C) + lane);
    float4 v;
    v.x = fmaf(acc.x, rc, x.x);
    v.y = fmaf(acc.y, rc, x.y);
    v.z = fmaf(acc.z, rc, x.z);
    v.w = fmaf(acc.w, rc, x.w);

    float m = v.x + v.y + v.z + v.w;
#pragma unroll
    for (int o = 16; o > 0; o >>= 1) m += __shfl_xor_sync(0xffffffffu, m, o);
    m *= (1.0f / C);

    float4 d;
    d.x = v.x - m; d.y = v.y - m; d.z = v.z - m; d.w = v.w - m;

    float var = d.x * d.x + d.y * d.y + d.z * d.z + d.w * d.w;
#pragma unroll
    for (int o = 16; o > 0; o >>= 1) var += __shfl_xor_sync(0xffffffffu, var, o);
    var *= (1.0f / C);

    float inv = rsqrtf(var + LN_EPS);

    float4 wv = __ldg(reinterpret_cast<const float4*>(lnw) + lane);
    float4 bv = __ldg(reinterpret_cast<const float4*>(lnb) + lane);

    float4 o4;
    o4.x = fmaf(d.x * inv, wv.x, bv.x);
    o4.y = fmaf(d.y * inv, wv.y, bv.y);
    o4.z = fmaf(d.z * inv, wv.z, bv.z);
    o4.w = fmaf(d.w * inv, wv.w, bv.w);

    if (do_relu) {
        o4.x = fmaxf(o4.x, 0.0f);
        o4.y = fmaxf(o4.y, 0.0f);
        o4.z = fmaxf(o4.z, 0.0f);
        o4.w = fmaxf(o4.w, 0.0f);
    }

    float4* dst = reinterpret_cast<float4*>(out + (size_t)gw * C) + lane;
    if (stream_out) {
        __stcs(dst, o4);     // evict-first: keep gather tables L2-resident
    } else {
        *dst = o4;
    }
}

extern "C" void kernel_launch(void* const* d_in, const int* in_sizes, int n_in,
                              void* d_out, int out_size) {
    const float* x_user = (const float*)d_in[0];
    const float* x_item = (const float*)d_in[1];
    const float* ew_ui  = (const float*)d_in[2];
    const float* ew_iu  = (const float*)d_in[3];
    const float* lnwu0  = (const float*)d_in[4];
    const float* lnbu0  = (const float*)d_in[5];
    const float* lnwu1  = (const float*)d_in[6];
    const float* lnbu1  = (const float*)d_in[7];
    const float* lnwi0  = (const float*)d_in[8];
    const float* lnbi0  = (const float*)d_in[9];
    const float* lnwi1  = (const float*)d_in[10];
    const float* lnbi1  = (const float*)d_in[11];
    const int*   ei_ui  = (const int*)d_in[12];
    const int*   ei_iu  = (const int*)d_in[13];
    float*       out    = (float*)d_out;

    int *deg, *off_u, *off_i, *cur_u, *cur_i, *bsum_u, *bsum_i;
    int2 *csr_iu, *csr_ui;
    float *u1, *i1;
    cudaGetSymbolAddress((void**)&deg, g_deg);
    cudaGetSymbolAddress((void**)&off_u, g_off_u);
    cudaGetSymbolAddress((void**)&off_i, g_off_i);
    cudaGetSymbolAddress((void**)&cur_u, g_cur_u);
    cudaGetSymbolAddress((void**)&cur_i, g_cur_i);
    cudaGetSymbolAddress((void**)&bsum_u, g_bsum_u);
    cudaGetSymbolAddress((void**)&bsum_i, g_bsum_i);
    cudaGetSymbolAddress((void**)&csr_iu, g_csr_iu);
    cudaGetSymbolAddress((void**)&csr_ui, g_csr_ui);
    cudaGetSymbolAddress((void**)&u1, g_u1);
    cudaGetSymbolAddress((void**)&i1, g_i1);

    int* deg_u = deg;
    int* deg_i = deg + NU;

    const int GC_U = NU / 8;     // warp per node, 8 warps/block
    const int GC_I = NI / 8;

    // ---- CSR build (layer-invariant; u/i pairs run concurrently) ----
    cudaMemsetAsync(deg, 0, 2 * NU * sizeof(int));
    count_both_kernel<<<(2 * EE + 255) / 256, 256>>>(
        ei_iu + EE, ei_ui + EE, deg_u, deg_i);

    {
        dim3 g1(NBLK, 2);
        scan1_kernel<<<g1, SCAN_T>>>(deg_u, off_u, bsum_u, deg_i, off_i, bsum_i);
        scan2_kernel<<<2, 256>>>(bsum_u, bsum_i);
        dim3 g3((NU + 255) / 256, 2);
        scan3_kernel<<<g3, 256>>>(off_u, bsum_u, cur_u, off_i, bsum_i, cur_i);
    }

    fill_both_kernel<<<(2 * EE + 255) / 256, 256>>>(
        ei_iu, ew_iu, cur_u, csr_iu, ei_ui, ew_ui, cur_i, csr_ui);

    // ---- layer 0 (outputs re-read next layer: normal cached stores) ----
    gather_combine_kernel<<<GC_U, 256>>>(off_u, csr_iu, x_item, x_user,
                                         lnwu0, lnbu0, u1, NU, 1, 0);
    gather_combine_kernel<<<GC_I, 256>>>(off_i, csr_ui, x_user, x_item,
                                         lnwi0, lnbi0, i1, NI, 1, 0);

    // ---- layer 1 (final outputs never re-read: streaming stores) ----
    gather_combine_kernel<<<GC_U, 256>>>(off_u, csr_iu, i1, u1,
                                         lnwu1, lnbu1, out, NU, 0, 1);
    gather_combine_kernel<<<GC_I, 256>>>(off_i, csr_ui, u1, i1,
                                         lnwi1, lnbi1, out + (size_t)NU * C,
                                         NI, 0, 1);
}

// round 9
// speedup vs baseline: 1.3227x; 1.0013x over previous
#include <cuda_runtime.h>
#include <cuda_bf16.h>

#define NU 100000
#define NI 100000
#define EE 1600000
#define C  128
#define LN_EPS 1e-5f

#define SCAN_T     256
#define SCAN_E     4
#define SCAN_CHUNK (SCAN_T * SCAN_E)   // 1024
#define NBLK ((NU + SCAN_CHUNK - 1) / SCAN_CHUNK)   // 98 (NU == NI)

// ---- scratch (allocation-free rule: device globals) ----
__device__ int   g_deg[2 * NU];          // [0,NU)=user, [NU,2NU)=item
__device__ int   g_off_u[NU + 1];
__device__ int   g_off_i[NI + 1];
__device__ int   g_cur_u[NU];
__device__ int   g_cur_i[NI];
__device__ int   g_bsum_u[NBLK];
__device__ int   g_bsum_i[NBLK];
__device__ int2  g_csr_iu[EE];   // edges into user nodes: {src_item, w}
__device__ int2  g_csr_ui[EE];   // edges into item nodes: {src_user, w}
__device__ float g_u1[(size_t)NU * C];
__device__ float g_i1[(size_t)NI * C];

// ---------------------------------------------------------------------------
// in-degree histogram, both edge types in one launch (independent arrays)
// ---------------------------------------------------------------------------
__global__ void count_both_kernel(const int* __restrict__ dst_u,
                                  const int* __restrict__ dst_i,
                                  int* __restrict__ deg_u,
                                  int* __restrict__ deg_i) {
    int e = blockIdx.x * blockDim.x + threadIdx.x;
    if (e < EE) {
        atomicAdd(&deg_u[__ldg(dst_u + e)], 1);
    } else if (e < 2 * EE) {
        atomicAdd(&deg_i[__ldg(dst_i + (e - EE))], 1);
    }
}

// ---------------------------------------------------------------------------
// prefix scan, u/i pairs fused via blockIdx.y; scan2 folded into scan3
// ---------------------------------------------------------------------------
__global__ void scan1_kernel(const int* __restrict__ in_u, int* __restrict__ out_u,
                             int* __restrict__ bsum_u,
                             const int* __restrict__ in_i, int* __restrict__ out_i,
                             int* __restrict__ bsum_i) {
    const int* in  = blockIdx.y ? in_i  : in_u;
    int*       out = blockIdx.y ? out_i : out_u;
    int*      bsum = blockIdx.y ? bsum_i : bsum_u;
    const int N = NU;

    __shared__ int sh[SCAN_T];
    int base = blockIdx.x * SCAN_CHUNK + threadIdx.x * SCAN_E;
    int v[SCAN_E];
    int s = 0;
#pragma unroll
    for (int i = 0; i < SCAN_E; i++) {
        int idx = base + i;
        v[i] = (idx < N) ? in[idx] : 0;
        s += v[i];
    }
    sh[threadIdx.x] = s;
    __syncthreads();
    for (int o = 1; o < SCAN_T; o <<= 1) {
        int val = sh[threadIdx.x];
        int add = (threadIdx.x >= o) ? sh[threadIdx.x - o] : 0;
        __syncthreads();
        sh[threadIdx.x] = val + add;
        __syncthreads();
    }
    int run = sh[threadIdx.x] - s;
#pragma unroll
    for (int i = 0; i < SCAN_E; i++) {
        int idx = base + i;
        if (idx < N) out[idx] = run;
        run += v[i];
    }
    if (threadIdx.x == SCAN_T - 1) bsum[blockIdx.x] = sh[SCAN_T - 1];
}

// adds block-sum prefixes (computed in-block from raw sums), finalizes off[N],
// and initializes the fill cursors. Replaces the old scan2+scan3 pair.
__global__ void scan3_kernel(int* __restrict__ off_u, const int* __restrict__ bsum_u,
                             int* __restrict__ cur_u,
                             int* __restrict__ off_i, const int* __restrict__ bsum_i,
                             int* __restrict__ cur_i) {
    int*       off  = blockIdx.y ? off_i  : off_u;
    const int* bsum = blockIdx.y ? bsum_i : bsum_u;
    int*       cur  = blockIdx.y ? cur_i  : cur_u;
    const int N = NU;

    __shared__ int sh[NBLK];
    int t = threadIdx.x;
    if (t < NBLK) sh[t] = bsum[t];
    __syncthreads();
    if (t == 0) {
        int run = 0;
#pragma unroll 1
        for (int j = 0; j < NBLK; j++) { int x = sh[j]; sh[j] = run; run += x; }
    }
    __syncthreads();

    int i = blockIdx.x * blockDim.x + t;
    if (i < N) {
        int v = off[i] + sh[i / SCAN_CHUNK];
        off[i] = v;
        cur[i] = v;
    }
    if (i == 0) off[N] = EE;
}

// ---------------------------------------------------------------------------
// CSR fill, both edge types in one launch. Edge arrays are on their LAST read
// here -> evict-first loads keep L2 free for the CSR the gathers need next.
// ---------------------------------------------------------------------------
__global__ void fill_both_kernel(const int* __restrict__ ei_iu,
                                 const float* __restrict__ ew_iu,
                                 int* __restrict__ cur_u, int2* __restrict__ csr_iu,
                                 const int* __restrict__ ei_ui,
                                 const float* __restrict__ ew_ui,
                                 int* __restrict__ cur_i, int2* __restrict__ csr_ui) {
    int e = blockIdx.x * blockDim.x + threadIdx.x;
    if (e < EE) {
        int src = __ldcs(ei_iu + e);
        int dst = __ldcs(ei_iu + EE + e);
        float w = __ldcs(ew_iu + e);
        int pos = atomicAdd(&cur_u[dst], 1);
        csr_iu[pos] = make_int2(src, __float_as_int(w));
    } else if (e < 2 * EE) {
        e -= EE;
        int src = __ldcs(ei_ui + e);
        int dst = __ldcs(ei_ui + EE + e);
        float w = __ldcs(ew_ui + e);
        int pos = atomicAdd(&cur_i[dst], 1);
        csr_ui[pos] = make_int2(src, __float_as_int(w));
    }
}

// ---------------------------------------------------------------------------
// fused gather + mean + root + LayerNorm (+ReLU). One warp per dst node.
// EXACT R2 body (unroll 2) — empirically optimal; do not change.
// Root read is read-once streaming -> __ldcs. Final-layer store -> __stcs.
// ---------------------------------------------------------------------------
__global__ void gather_combine_kernel(const int* __restrict__ off,
                                      const int2* __restrict__ csr,
                                      const float* __restrict__ xsrc,
                                      const float* __restrict__ xdst,
                                      const float* __restrict__ lnw,
                                      const float* __restrict__ lnb,
                                      float* __restrict__ out,
                                      int N, int do_relu, int stream_out) {
    int gw   = (blockIdx.x * blockDim.x + threadIdx.x) >> 5;
    int lane = threadIdx.x & 31;
    if (gw >= N) return;

    int beg = __ldg(off + gw);
    int end = __ldg(off + gw + 1);

    float4 acc = make_float4(0.f, 0.f, 0.f, 0.f);
    int e = beg;
    for (; e + 1 < end; e += 2) {
        int2 p0 = __ldg(csr + e);
        int2 p1 = __ldg(csr + e + 1);
        float4 v0 = __ldg(reinterpret_cast<const float4*>(xsrc + (size_t)p0.x * C) + lane);
        float4 v1 = __ldg(reinterpret_cast<const float4*>(xsrc + (size_t)p1.x * C) + lane);
        float w0 = __int_as_float(p0.y);
        float w1 = __int_as_float(p1.y);
        acc.x = fmaf(w0, v0.x, acc.x); acc.y = fmaf(w0, v0.y, acc.y);
        acc.z = fmaf(w0, v0.z, acc.z); acc.w = fmaf(w0, v0.w, acc.w);
        acc.x = fmaf(w1, v1.x, acc.x); acc.y = fmaf(w1, v1.y, acc.y);
        acc.z = fmaf(w1, v1.z, acc.z); acc.w = fmaf(w1, v1.w, acc.w);
    }
    if (e < end) {
        int2 p0 = __ldg(csr + e);
        float4 v0 = __ldg(reinterpret_cast<const float4*>(xsrc + (size_t)p0.x * C) + lane);
        float w0 = __int_as_float(p0.y);
        acc.x = fmaf(w0, v0.x, acc.x); acc.y = fmaf(w0, v0.y, acc.y);
        acc.z = fmaf(w0, v0.z, acc.z); acc.w = fmaf(w0, v0.w, acc.w);
    }

    float rc = 1.0f / fmaxf((float)(end - beg), 1.0f);

    float4 x = __ldcs(reinterpret_cast<const float4*>(xdst + (size_t)gw * C) + lane);
    float4 v;
    v.x = fmaf(acc.x, rc, x.x);
    v.y = fmaf(acc.y, rc, x.y);
    v.z = fmaf(acc.z, rc, x.z);
    v.w = fmaf(acc.w, rc, x.w);

    float m = v.x + v.y + v.z + v.w;
#pragma unroll
    for (int o = 16; o > 0; o >>= 1) m += __shfl_xor_sync(0xffffffffu, m, o);
    m *= (1.0f / C);

    float4 d;
    d.x = v.x - m; d.y = v.y - m; d.z = v.z - m; d.w = v.w - m;

    float var = d.x * d.x + d.y * d.y + d.z * d.z + d.w * d.w;
#pragma unroll
    for (int o = 16; o > 0; o >>= 1) var += __shfl_xor_sync(0xffffffffu, var, o);
    var *= (1.0f / C);

    float inv = rsqrtf(var + LN_EPS);

    float4 wv = __ldg(reinterpret_cast<const float4*>(lnw) + lane);
    float4 bv = __ldg(reinterpret_cast<const float4*>(lnb) + lane);

    float4 o4;
    o4.x = fmaf(d.x * inv, wv.x, bv.x);
    o4.y = fmaf(d.y * inv, wv.y, bv.y);
    o4.z = fmaf(d.z * inv, wv.z, bv.z);
    o4.w = fmaf(d.w * inv, wv.w, bv.w);

    if (do_relu) {
        o4.x = fmaxf(o4.x, 0.0f);
        o4.y = fmaxf(o4.y, 0.0f);
        o4.z = fmaxf(o4.z, 0.0f);
        o4.w = fmaxf(o4.w, 0.0f);
    }

    float4* dst = reinterpret_cast<float4*>(out + (size_t)gw * C) + lane;
    if (stream_out) {
        __stcs(dst, o4);     // evict-first: keep gather tables L2-resident
    } else {
        *dst = o4;
    }
}

extern "C" void kernel_launch(void* const* d_in, const int* in_sizes, int n_in,
                              void* d_out, int out_size) {
    const float* x_user = (const float*)d_in[0];
    const float* x_item = (const float*)d_in[1];
    const float* ew_ui  = (const float*)d_in[2];
    const float* ew_iu  = (const float*)d_in[3];
    const float* lnwu0  = (const float*)d_in[4];
    const float* lnbu0  = (const float*)d_in[5];
    const float* lnwu1  = (const float*)d_in[6];
    const float* lnbu1  = (const float*)d_in[7];
    const float* lnwi0  = (const float*)d_in[8];
    const float* lnbi0  = (const float*)d_in[9];
    const float* lnwi1  = (const float*)d_in[10];
    const float* lnbi1  = (const float*)d_in[11];
    const int*   ei_ui  = (const int*)d_in[12];
    const int*   ei_iu  = (const int*)d_in[13];
    float*       out    = (float*)d_out;

    int *deg, *off_u, *off_i, *cur_u, *cur_i, *bsum_u, *bsum_i;
    int2 *csr_iu, *csr_ui;
    float *u1, *i1;
    cudaGetSymbolAddress((void**)&deg, g_deg);
    cudaGetSymbolAddress((void**)&off_u, g_off_u);
    cudaGetSymbolAddress((void**)&off_i, g_off_i);
    cudaGetSymbolAddress((void**)&cur_u, g_cur_u);
    cudaGetSymbolAddress((void**)&cur_i, g_cur_i);
    cudaGetSymbolAddress((void**)&bsum_u, g_bsum_u);
    cudaGetSymbolAddress((void**)&bsum_i, g_bsum_i);
    cudaGetSymbolAddress((void**)&csr_iu, g_csr_iu);
    cudaGetSymbolAddress((void**)&csr_ui, g_csr_ui);
    cudaGetSymbolAddress((void**)&u1, g_u1);
    cudaGetSymbolAddress((void**)&i1, g_i1);

    int* deg_u = deg;
    int* deg_i = deg + NU;

    const int GC_U = NU / 8;     // warp per node, 8 warps/block
    const int GC_I = NI / 8;

    // ---- CSR build (layer-invariant; u/i pairs run concurrently) ----
    cudaMemsetAsync(deg, 0, 2 * NU * sizeof(int));
    count_both_kernel<<<(2 * EE + 255) / 256, 256>>>(
        ei_iu + EE, ei_ui + EE, deg_u, deg_i);

    {
        dim3 g1(NBLK, 2);
        scan1_kernel<<<g1, SCAN_T>>>(deg_u, off_u, bsum_u, deg_i, off_i, bsum_i);
        dim3 g3((NU + 255) / 256, 2);
        scan3_kernel<<<g3, 256>>>(off_u, bsum_u, cur_u, off_i, bsum_i, cur_i);
    }

    fill_both_kernel<<<(2 * EE + 255) / 256, 256>>>(
        ei_iu, ew_iu, cur_u, csr_iu, ei_ui, ew_ui, cur_i, csr_ui);

    // ---- layer 0 (outputs re-read next layer: normal cached stores) ----
    gather_combine_kernel<<<GC_U, 256>>>(off_u, csr_iu, x_item, x_user,
                                         lnwu0, lnbu0, u1, NU, 1, 0);
    gather_combine_kernel<<<GC_I, 256>>>(off_i, csr_ui, x_user, x_item,
                                         lnwi0, lnbi0, i1, NI, 1, 0);

    // ---- layer 1 (final outputs never re-read: streaming stores) ----
    gather_combine_kernel<<<GC_U, 256>>>(off_u, csr_iu, i1, u1,
                                         lnwu1, lnbu1, out, NU, 0, 1);
    gather_combine_kernel<<<GC_I, 256>>>(off_i, csr_ui, u1, i1,
                                         lnwi1, lnbi1, out + (size_t)NU * C,
                                         NI, 0, 1);
}